// round 3
// baseline (speedup 1.0000x reference)
#include <cuda_runtime.h>

// ROI max pooling, matching the JAX reference exactly.
// feat: [N_IMG=2, C=256, H=38, W=38] f32
// rois: [NUM_ROIS=256, 5] f32  (batch_idx, x1, y1, x2, y2) in image coords
// out : [NUM_ROIS, C, 7, 7] f32
//
// Per bin:
//   x1 = floor(roi_x1 * 0.0625) etc. (int)
//   rh = y2 - y1 + 1, rw = x2 - x1 + 1
//   hstart = y1 + (i*rh)/7,  hend = y1 + ceil((i+1)*rh/7)
//   out = max over feat[b, c, hstart:hend, wstart:wend]
//
// Given the input distribution (coords in [0, 607.9], scale 1/16), all
// windows fall inside [0,38) and are non-empty, so no clamping is needed
// and the plain max over the rectangle equals the reference masked max.

#define N_IMG 2
#define CHN   256
#define H_    38
#define W_    38
#define NUM_ROIS 256
#define OUT_H 7
#define OUT_W 7
#define SPATIAL_SCALE 0.0625f

__global__ void roi_pool_kernel(const float* __restrict__ feat,
                                const float* __restrict__ rois,
                                float* __restrict__ out,
                                int total)
{
    int idx = blockIdx.x * blockDim.x + threadIdx.x;
    if (idx >= total) return;

    // idx -> (roi, c, i, j), j fastest (matches output layout -> coalesced store)
    int bin = idx % (OUT_H * OUT_W);
    int t   = idx / (OUT_H * OUT_W);
    int c   = t % CHN;
    int roi = t / CHN;
    int i   = bin / OUT_W;
    int j   = bin % OUT_W;

    const float* r = rois + roi * 5;
    int b  = (int)r[0];
    int x1 = (int)floorf(r[1] * SPATIAL_SCALE);
    int y1 = (int)floorf(r[2] * SPATIAL_SCALE);
    int x2 = (int)floorf(r[3] * SPATIAL_SCALE);
    int y2 = (int)floorf(r[4] * SPATIAL_SCALE);

    int rh = y2 - y1 + 1;
    int rw = x2 - x1 + 1;

    int hstart = y1 + (i * rh) / OUT_H;
    int hend   = y1 + ((i + 1) * rh + OUT_H - 1) / OUT_H;
    int wstart = x1 + (j * rw) / OUT_W;
    int wend   = x1 + ((j + 1) * rw + OUT_W - 1) / OUT_W;

    const float* fp = feat + ((size_t)(b * CHN + c)) * (H_ * W_);

    float m = -__int_as_float(0x7f800000);  // -inf
    for (int h = hstart; h < hend; ++h) {
        const float* row = fp + h * W_;
        for (int w = wstart; w < wend; ++w) {
            m = fmaxf(m, __ldg(row + w));
        }
    }
    out[idx] = m;
}

extern "C" void kernel_launch(void* const* d_in, const int* in_sizes, int n_in,
                              void* d_out, int out_size)
{
    const float* feat = (const float*)d_in[0];
    const float* rois = (const float*)d_in[1];
    float* out = (float*)d_out;

    int total = out_size;  // NUM_ROIS * CHN * OUT_H * OUT_W
    int threads = 256;
    int blocks = (total + threads - 1) / threads;
    roi_pool_kernel<<<blocks, threads>>>(feat, rois, out, total);
}